// round 1
// baseline (speedup 1.0000x reference)
#include <cuda_runtime.h>
#include <cuda_bf16.h>
#include <math.h>

// ---------------------------------------------------------------------------
// SelfReferentialField: two MoE engines + self-referential tension loop.
// Shapes: B=2048, IN=1024, HID=2048, OUT=1024, N_EXP_A=12 (top-4), N_EXP_G=6.
// All fp32. Strategy: route EngineA tokens (top-4 of 12) to cut FLOPs 3x on A,
// classic 128x128x8 shared-memory SGEMM with fused epilogues.
// ---------------------------------------------------------------------------

#define BATCH   2048
#define IN_DIM  1024
#define HID_DIM 2048
#define OUT_DIM 1024
#define NEXPA   12
#define TOPKA   4
#define NEXPG   6

// H_TARGET = -(0.5 ln 0.5 + (1/3) ln(1/3) + (1/6) ln(1/6))
#define H_TARGET 1.0114042647073518f

// ------------------------- device scratch (static) -------------------------
__device__ float g_h     [BATCH * HID_DIM];   // per-expert hidden (reused)
__device__ float g_out_p [BATCH * OUT_DIM];   // out_plus
__device__ float g_out_m [BATCH * OUT_DIM];   // out_minus
__device__ float g_rep   [BATCH * OUT_DIM];   // repulsion
__device__ float g_mr    [BATCH * OUT_DIM];   // modified repulsion
__device__ float g_ss    [BATCH * OUT_DIM];   // self_state
__device__ float g_h1    [BATCH * HID_DIM];   // self-model hidden
__device__ float g_wa    [BATCH * NEXPA];     // dense A weights (zeros except top4)
__device__ float g_wg    [BATCH * NEXPG];     // G softmax weights
__device__ float g_ent   [BATCH];             // per-token entropy
__device__ float g_pt    [BATCH];             // prev_tension per row
__device__ float g_tens  [8];                 // tensions[0..3]
__device__ int   g_cnt   [NEXPA];             // routed counts per A expert
__device__ int   g_list  [NEXPA * BATCH];     // routed token ids
__device__ float g_wcomp [NEXPA * BATCH];     // routed weights

// ------------------------------ helpers ------------------------------------
__device__ __forceinline__ float block_reduce_sum(float v) {
    __shared__ float s[32];
    int lane = threadIdx.x & 31, w = threadIdx.x >> 5;
    #pragma unroll
    for (int o = 16; o > 0; o >>= 1) v += __shfl_down_sync(0xffffffffu, v, o);
    if (lane == 0) s[w] = v;
    __syncthreads();
    int nw = blockDim.x >> 5;
    v = (threadIdx.x < nw) ? s[threadIdx.x] : 0.f;
    if (w == 0) {
        #pragma unroll
        for (int o = 16; o > 0; o >>= 1) v += __shfl_down_sync(0xffffffffu, v, o);
    }
    return v;  // valid on thread 0
}

// ------------------------------ zero ----------------------------------------
__global__ void zero_kernel() {
    int i = blockIdx.x * blockDim.x + threadIdx.x;
    if (i < BATCH * OUT_DIM) { g_out_p[i] = 0.f; g_out_m[i] = 0.f; }
}

// ------------------------------ gating --------------------------------------
// One block per token: 18 dot products of length 1024, then top-4 softmax (A),
// dense softmax + entropy (G).
__global__ __launch_bounds__(256) void gate_kernel(
    const float* __restrict__ x,
    const float* __restrict__ gaw, const float* __restrict__ gab,
    const float* __restrict__ ggw, const float* __restrict__ ggb)
{
    int b = blockIdx.x;
    int tid = threadIdx.x;
    float acc[18];
    #pragma unroll
    for (int e = 0; e < 18; e++) acc[e] = 0.f;
    const float* xr = x + (size_t)b * IN_DIM;
    for (int i = tid; i < IN_DIM; i += 256) {
        float xv = xr[i];
        #pragma unroll
        for (int e = 0; e < NEXPA; e++) acc[e] = fmaf(xv, gaw[i * NEXPA + e], acc[e]);
        #pragma unroll
        for (int e = 0; e < NEXPG; e++) acc[12 + e] = fmaf(xv, ggw[i * NEXPG + e], acc[12 + e]);
    }
    __shared__ float s[18][8];
    int lane = tid & 31, w = tid >> 5;
    #pragma unroll
    for (int e = 0; e < 18; e++) {
        float v = acc[e];
        #pragma unroll
        for (int o = 16; o > 0; o >>= 1) v += __shfl_down_sync(0xffffffffu, v, o);
        if (lane == 0) s[e][w] = v;
    }
    __syncthreads();
    if (tid == 0) {
        float logits[18];
        for (int e = 0; e < 18; e++) {
            float v = 0.f;
            for (int ww = 0; ww < 8; ww++) v += s[e][ww];
            logits[e] = v + (e < 12 ? gab[e] : ggb[e - 12]);
        }
        // ---- top-4 of A ----
        bool used[NEXPA];
        for (int e = 0; e < NEXPA; e++) used[e] = false;
        int   idxs[TOPKA];
        float vals[TOPKA];
        for (int k = 0; k < TOPKA; k++) {
            int bi = -1; float bv = -INFINITY;
            for (int e = 0; e < NEXPA; e++)
                if (!used[e] && logits[e] > bv) { bv = logits[e]; bi = e; }
            used[bi] = true; idxs[k] = bi; vals[k] = bv;
        }
        float m = vals[0], sum = 0.f, wv[TOPKA];
        for (int k = 0; k < TOPKA; k++) { wv[k] = expf(vals[k] - m); sum += wv[k]; }
        for (int e = 0; e < NEXPA; e++) g_wa[b * NEXPA + e] = 0.f;
        for (int k = 0; k < TOPKA; k++) g_wa[b * NEXPA + idxs[k]] = wv[k] / sum;
        // ---- G softmax + entropy ----
        float mg = -INFINITY;
        for (int e = 0; e < NEXPG; e++) mg = fmaxf(mg, logits[12 + e]);
        float sg = 0.f, eg[NEXPG];
        for (int e = 0; e < NEXPG; e++) { eg[e] = expf(logits[12 + e] - mg); sg += eg[e]; }
        float ent = 0.f;
        for (int e = 0; e < NEXPG; e++) {
            float wge = eg[e] / sg;
            g_wg[b * NEXPG + e] = wge;
            ent -= wge * logf(wge + 1e-8f);
        }
        g_ent[b] = ent;
    }
}

// ------------------------------ routing -------------------------------------
// 12 warps, warp e compacts tokens with weight>0 deterministically via ballot.
__global__ void route_kernel() {
    int wid = threadIdx.x >> 5, lane = threadIdx.x & 31;
    if (wid >= NEXPA) return;
    int cnt = 0;
    for (int base = 0; base < BATCH; base += 32) {
        int b = base + lane;
        float w = g_wa[b * NEXPA + wid];
        bool sel = (w > 0.f);
        unsigned m = __ballot_sync(0xffffffffu, sel);
        if (sel) {
            int pos = cnt + __popc(m & ((1u << lane) - 1u));
            g_list[wid * BATCH + pos]  = b;
            g_wcomp[wid * BATCH + pos] = w;
        }
        cnt += __popc(m);
    }
    if (lane == 0) g_cnt[wid] = cnt;
}

// ------------------------------ SGEMM ---------------------------------------
// 128x128 tile, BK=8, 256 threads, 8x8 micro-tile.
// MODE 0: C = relu(A@B + bias)                 (store to compact rows)
// MODE 1: C[rowsC[m]] += w[m]*(A@B + bias)     (scatter weighted accumulate)
// MODE 2: C = tanh(A@B + bias)
// MODE 3: C = addend + A@B + bias
// MODE 4: C = 0.5*(ex1+ex2) + tscale*sqrt(pt[m]+1e-8)*tanh(A@B + bias)
#define BM 128
#define BN 128
#define BKD 8

template<int MODE>
__global__ __launch_bounds__(256) void gemm_k(
    const float* __restrict__ A, const float* __restrict__ B,
    const float* __restrict__ bias, float* __restrict__ C,
    const int* __restrict__ rowsA, const int* __restrict__ rowsC,
    const float* __restrict__ wvec, int wstride,
    const float* __restrict__ addend,
    const float* __restrict__ ex1, const float* __restrict__ ex2,
    const float* __restrict__ pt, const float* __restrict__ tscale,
    const int* __restrict__ cntPtr,
    int M, int K, int N)
{
    int Mtot = cntPtr ? *cntPtr : M;
    int bm = blockIdx.y * BM;
    if (bm >= Mtot) return;
    int bn = blockIdx.x * BN;

    __shared__ __align__(16) float As[BKD * 132];
    __shared__ __align__(16) float Bs[BKD * 128];

    int tid = threadIdx.x;
    int aRow = tid >> 1;
    int aCol = (tid & 1) * 4;
    int gm = bm + aRow;
    bool aValid = (gm < Mtot);
    int arow_actual = aValid ? (rowsA ? rowsA[gm] : gm) : 0;
    const float* aPtr = A + (size_t)arow_actual * K + aCol;

    int bRow = tid >> 5;
    int bCol = (tid & 31) * 4;
    const float* bPtr = B + (size_t)bRow * N + bn + bCol;

    float acc[8][8];
    #pragma unroll
    for (int i = 0; i < 8; i++)
        #pragma unroll
        for (int j = 0; j < 8; j++) acc[i][j] = 0.f;

    int ty = tid >> 4, tx = tid & 15;

    for (int k0 = 0; k0 < K; k0 += BKD) {
        float4 av = aValid ? *(const float4*)(aPtr + k0) : make_float4(0.f, 0.f, 0.f, 0.f);
        float4 bv = *(const float4*)(bPtr + (size_t)k0 * N);
        __syncthreads();
        As[(aCol + 0) * 132 + aRow] = av.x;
        As[(aCol + 1) * 132 + aRow] = av.y;
        As[(aCol + 2) * 132 + aRow] = av.z;
        As[(aCol + 3) * 132 + aRow] = av.w;
        *(float4*)&Bs[bRow * 128 + bCol] = bv;
        __syncthreads();
        #pragma unroll
        for (int k = 0; k < BKD; k++) {
            float4 a0 = *(const float4*)&As[k * 132 + ty * 8];
            float4 a1 = *(const float4*)&As[k * 132 + ty * 8 + 4];
            float4 b0 = *(const float4*)&Bs[k * 128 + tx * 8];
            float4 b1 = *(const float4*)&Bs[k * 128 + tx * 8 + 4];
            float a[8] = {a0.x, a0.y, a0.z, a0.w, a1.x, a1.y, a1.z, a1.w};
            float b[8] = {b0.x, b0.y, b0.z, b0.w, b1.x, b1.y, b1.z, b1.w};
            #pragma unroll
            for (int i = 0; i < 8; i++)
                #pragma unroll
                for (int j = 0; j < 8; j++)
                    acc[i][j] = fmaf(a[i], b[j], acc[i][j]);
        }
    }

    #pragma unroll
    for (int i = 0; i < 8; i++) {
        int m = bm + ty * 8 + i;
        if (m >= Mtot) continue;
        int crow = m;
        float rw = 1.f, scale = 0.f;
        if (MODE == 1) {
            if (rowsC) crow = rowsC[m];
            rw = wvec[m * wstride];
        }
        if (MODE == 4) scale = tscale[0] * sqrtf(pt[m] + 1e-8f);
        #pragma unroll
        for (int j = 0; j < 8; j++) {
            int n = bn + tx * 8 + j;
            float v = acc[i][j] + bias[n];
            size_t idx = (size_t)crow * N + n;
            if (MODE == 0)      C[idx] = fmaxf(v, 0.f);
            else if (MODE == 1) C[idx] += rw * v;
            else if (MODE == 2) C[idx] = tanhf(v);
            else if (MODE == 3) C[idx] = addend[(size_t)m * N + n] + v;
            else if (MODE == 4) {
                float fd = tanhf(v);
                C[idx] = 0.5f * (ex1[idx] + ex2[idx]) + scale * fd;
            }
        }
    }
}

// ---------------------- repulsion / tension reductions ----------------------
__global__ __launch_bounds__(256) void rep_kernel() {
    int b = blockIdx.x;
    float ss = 0.f;
    for (int n = threadIdx.x; n < OUT_DIM; n += 256) {
        size_t i = (size_t)b * OUT_DIM + n;
        float r = g_out_p[i] - g_out_m[i];
        g_rep[i] = r;
        ss += r * r;
    }
    float tot = block_reduce_sum(ss);
    if (threadIdx.x == 0) g_pt[b] = tot;
}

__global__ __launch_bounds__(256) void sumsq_kernel() {
    int b = blockIdx.x;
    float ss = 0.f;
    for (int n = threadIdx.x; n < OUT_DIM; n += 256) {
        float r = g_mr[(size_t)b * OUT_DIM + n];
        ss += r * r;
    }
    float tot = block_reduce_sum(ss);
    if (threadIdx.x == 0) g_pt[b] = tot;
}

__global__ __launch_bounds__(256) void mean_kernel(const float* __restrict__ src,
                                                   float* __restrict__ dst) {
    float s = 0.f;
    for (int i = threadIdx.x; i < BATCH; i += 256) s += src[i];
    float tot = block_reduce_sum(s);
    if (threadIdx.x == 0) dst[0] = tot * (1.f / (float)BATCH);
}

// ------------------------- self-model hidden layer --------------------------
// h1[b,j] = tanh(si0*w1[0,j] + si1*w1[1,j] + si2*w1[2,j] + b1[j])
__global__ __launch_bounds__(256) void h1_kernel(const float* __restrict__ w1,
                                                 const float* __restrict__ b1,
                                                 int step) {
    int idx = blockIdx.x * blockDim.x + threadIdx.x;
    if (idx >= BATCH * HID_DIM) return;
    int b = idx >> 11;       // /2048
    int j = idx & 2047;
    float t  = g_pt[b];
    float d  = (step == 0) ? 0.f : (t - g_tens[step]);
    float sv = (float)step * (1.f / 3.f);
    float v = t * w1[j] + d * w1[HID_DIM + j] + sv * w1[2 * HID_DIM + j] + b1[j];
    g_h1[idx] = tanhf(v);
}

// ------------------------------ aux loss ------------------------------------
__global__ __launch_bounds__(256) void aux_kernel(float* __restrict__ out, int out_size) {
    float s = 0.f;
    for (int i = threadIdx.x; i < BATCH; i += 256) s += g_ent[i];
    float tot = block_reduce_sum(s);
    if (threadIdx.x == 0) {
        float h  = tot * (1.f / (float)BATCH);
        float el = (h - H_TARGET) * (h - H_TARGET);
        float conv = (fabsf(g_tens[1] - g_tens[0]) +
                      fabsf(g_tens[2] - g_tens[1]) +
                      fabsf(g_tens[3] - g_tens[2])) * (1.f / 3.f);
        float aux = el + 0.001f * conv;
        for (int j = BATCH * OUT_DIM; j < out_size; j++) out[j] = aux;
    }
}

// ------------------------------ launcher ------------------------------------
extern "C" void kernel_launch(void* const* d_in, const int* in_sizes, int n_in,
                              void* d_out, int out_size) {
    (void)in_sizes; (void)n_in;
    const float* x    = (const float*)d_in[0];
    const float* gaw  = (const float*)d_in[1];
    const float* gab  = (const float*)d_in[2];
    const float* wa1  = (const float*)d_in[3];
    const float* ba1  = (const float*)d_in[4];
    const float* wa2  = (const float*)d_in[5];
    const float* ba2  = (const float*)d_in[6];
    const float* ggw  = (const float*)d_in[7];
    const float* ggb  = (const float*)d_in[8];
    const float* wg1  = (const float*)d_in[9];
    const float* bg1  = (const float*)d_in[10];
    const float* wg2  = (const float*)d_in[11];
    const float* bg2  = (const float*)d_in[12];
    const float* smw1 = (const float*)d_in[13];
    const float* smb1 = (const float*)d_in[14];
    const float* smw2 = (const float*)d_in[15];
    const float* smb2 = (const float*)d_in[16];
    const float* siw  = (const float*)d_in[17];
    const float* sib  = (const float*)d_in[18];
    const float* ftw  = (const float*)d_in[19];
    const float* ftb  = (const float*)d_in[20];
    const float* tsc  = (const float*)d_in[21];
    float* out = (float*)d_out;

    float *p_h, *p_op, *p_om, *p_rep, *p_mr, *p_ss, *p_h1, *p_pt, *p_tens, *p_wg, *p_wcomp;
    int *p_cnt, *p_list;
    cudaGetSymbolAddress((void**)&p_h,     g_h);
    cudaGetSymbolAddress((void**)&p_op,    g_out_p);
    cudaGetSymbolAddress((void**)&p_om,    g_out_m);
    cudaGetSymbolAddress((void**)&p_rep,   g_rep);
    cudaGetSymbolAddress((void**)&p_mr,    g_mr);
    cudaGetSymbolAddress((void**)&p_ss,    g_ss);
    cudaGetSymbolAddress((void**)&p_h1,    g_h1);
    cudaGetSymbolAddress((void**)&p_pt,    g_pt);
    cudaGetSymbolAddress((void**)&p_tens,  g_tens);
    cudaGetSymbolAddress((void**)&p_wg,    g_wg);
    cudaGetSymbolAddress((void**)&p_wcomp, g_wcomp);
    cudaGetSymbolAddress((void**)&p_cnt,   g_cnt);
    cudaGetSymbolAddress((void**)&p_list,  g_list);

    zero_kernel<<<(BATCH * OUT_DIM + 255) / 256, 256>>>();
    gate_kernel<<<BATCH, 256>>>(x, gaw, gab, ggw, ggb);
    route_kernel<<<1, NEXPA * 32>>>();

    dim3 gH(HID_DIM / BN, BATCH / BM);   // N=2048 GEMMs
    dim3 gO(OUT_DIM / BN, BATCH / BM);   // N=1024 GEMMs

    // EngineA: routed experts
    for (int e = 0; e < NEXPA; e++) {
        gemm_k<0><<<gH, 256>>>(x, wa1 + (size_t)e * IN_DIM * HID_DIM, ba1 + e * HID_DIM,
                               p_h, p_list + e * BATCH, nullptr, nullptr, 0,
                               nullptr, nullptr, nullptr, nullptr, nullptr,
                               p_cnt + e, BATCH, IN_DIM, HID_DIM);
        gemm_k<1><<<gO, 256>>>(p_h, wa2 + (size_t)e * HID_DIM * OUT_DIM, ba2 + e * OUT_DIM,
                               p_op, nullptr, p_list + e * BATCH, p_wcomp + e * BATCH, 1,
                               nullptr, nullptr, nullptr, nullptr, nullptr,
                               p_cnt + e, BATCH, HID_DIM, OUT_DIM);
    }
    // EngineG: dense experts
    for (int e = 0; e < NEXPG; e++) {
        gemm_k<0><<<gH, 256>>>(x, wg1 + (size_t)e * IN_DIM * HID_DIM, bg1 + e * HID_DIM,
                               p_h, nullptr, nullptr, nullptr, 0,
                               nullptr, nullptr, nullptr, nullptr, nullptr,
                               nullptr, BATCH, IN_DIM, HID_DIM);
        gemm_k<1><<<gO, 256>>>(p_h, wg2 + (size_t)e * HID_DIM * OUT_DIM, bg2 + e * OUT_DIM,
                               p_om, nullptr, nullptr, p_wg + e, NEXPG,
                               nullptr, nullptr, nullptr, nullptr, nullptr,
                               nullptr, BATCH, HID_DIM, OUT_DIM);
    }

    rep_kernel<<<BATCH, 256>>>();
    mean_kernel<<<1, 256>>>(p_pt, p_tens + 0);

    for (int s = 0; s < 3; s++) {
        h1_kernel<<<(BATCH * HID_DIM + 255) / 256, 256>>>(smw1, smb1, s);
        gemm_k<2><<<gO, 256>>>(p_h1, smw2, smb2, p_ss,
                               nullptr, nullptr, nullptr, 0,
                               nullptr, nullptr, nullptr, nullptr, nullptr,
                               nullptr, BATCH, HID_DIM, OUT_DIM);
        gemm_k<3><<<gO, 256>>>(p_ss, siw, sib, p_mr,
                               nullptr, nullptr, nullptr, 0,
                               p_rep, nullptr, nullptr, nullptr, nullptr,
                               nullptr, BATCH, OUT_DIM, OUT_DIM);
        sumsq_kernel<<<BATCH, 256>>>();
        mean_kernel<<<1, 256>>>(p_pt, p_tens + s + 1);
    }

    gemm_k<4><<<gO, 256>>>(p_mr, ftw, ftb, out,
                           nullptr, nullptr, nullptr, 0,
                           nullptr, p_op, p_om, p_pt, tsc,
                           nullptr, BATCH, OUT_DIM, OUT_DIM);
    aux_kernel<<<1, 256>>>(out, out_size);
}